// round 5
// baseline (speedup 1.0000x reference)
#include <cuda_runtime.h>
#include <math.h>

#define E_    2048
#define S_    256
#define Q_    25
#define NN_   36
#define R_    15
#define H_    128
#define K2_   72           // 2*NN_
#define SR_   3840         // S_*R_
#define NPTS  (E_*NN_)     // 73728
#define PPB   64           // points per MLP block
#define MLP_BLOCKS (NPTS/PPB)   // 1152
#define STAGE1_BLOCKS (MLP_BLOCKS + S_)  // 1408
#define GX 30              // N tiles (3840/128)
#define GY 32              // M tiles (2048/64)
#define NPART (GX*GY)      // 960

#define ASTRIDE 68         // 64 + 4 pad (floats)
#define BDSTRIDE 130       // 128 + 2 pad (u64)

typedef unsigned long long u64t;

// ---- scratch ----
__device__ float g_evcat[E_*K2_];          // [E][72]
__device__ u64t  g_AcatT[K2_*SR_];         // [k][sr] duplicated pairs (acc,acc)
__device__ u64t  g_Wdup[2*H_*H_];          // W2,W3 as (w,w) u64, [l][k][j]
__device__ float g_partial[NPART];
__device__ unsigned g_count = 0;

// ---- packed f32x2 helpers ----
__device__ __forceinline__ u64t pk2(float lo, float hi){
    u64t r; asm("mov.b64 %0,{%1,%2};" : "=l"(r) : "f"(lo), "f"(hi)); return r;
}
__device__ __forceinline__ u64t fma2(u64t a, u64t b, u64t c){
    u64t d; asm("fma.rn.f32x2 %0,%1,%2,%3;" : "=l"(d) : "l"(a), "l"(b), "l"(c)); return d;
}
__device__ __forceinline__ void upk2(u64t x, float& lo, float& hi){
    asm("mov.b64 {%0,%1},%2;" : "=f"(lo), "=f"(hi) : "l"(x));
}
union F4U { float4 f; u64t u[2]; };

// fast tanh: 1 - 2/(exp(2x)+1)
__device__ __forceinline__ float fast_tanh(float x){
    float e;
    asm("ex2.approx.f32 %0, %1;" : "=f"(e) : "f"(x * 2.885390081777926f));
    float r;
    asm("rcp.approx.f32 %0, %1;" : "=f"(r) : "f"(e + 1.0f));
    return 1.0f - 2.0f * r;
}

// ============================================================
// Prologue: duplicate W2, W3 into (w,w) u64 pairs.
// ============================================================
__global__ void dup_w(const float* __restrict__ W2, const float* __restrict__ W3){
    int idx = blockIdx.x * blockDim.x + threadIdx.x;   // 0 .. 32767
    if (idx < H_*H_){
        float w = W2[idx];
        g_Wdup[idx] = pk2(w, w);
    } else {
        float w = W3[idx - H_*H_];
        g_Wdup[idx] = pk2(w, w);
    }
}

// ============================================================
// MLP layer on 64 points, 128 threads.
// Per thread: 4 m-pairs (8 m) x 8 n = 32 fma2, m-packed.
// Hout[j][p] = tanh(sum_k Hin[k][p]*W[k][j] + b[j])
// Wd: duplicated (w,w) pairs, [k][j].
// ============================================================
__device__ __forceinline__ void gemm_layer64(const float* __restrict__ Hin, float* __restrict__ Hout,
                                             const u64t* __restrict__ Wd, const float* __restrict__ b){
    const int tid = threadIdx.x;
    const int tx = tid & 15, ty = tid >> 4;   // n0 = tx*8 (128 n), m0 = ty*8 (64 m)
    const int m0 = ty * 8, n0 = tx * 8;

    u64t acc[4][8];
    #pragma unroll
    for (int j = 0; j < 8; j++){
        float bj = __ldg(&b[n0 + j]);
        u64t bb = pk2(bj, bj);
        #pragma unroll
        for (int mp = 0; mp < 4; mp++) acc[mp][j] = bb;
    }

    #pragma unroll 2
    for (int k = 0; k < H_; k++){
        F4U a0, a1;
        a0.f = *(const float4*)(Hin + k*ASTRIDE + m0);
        a1.f = *(const float4*)(Hin + k*ASTRIDE + m0 + 4);
        u64t ap[4] = { a0.u[0], a0.u[1], a1.u[0], a1.u[1] };
        const u64t* wr = Wd + k*H_ + n0;
        ulonglong2 w0 = __ldg((const ulonglong2*)(wr));
        ulonglong2 w1 = __ldg((const ulonglong2*)(wr + 2));
        ulonglong2 w2 = __ldg((const ulonglong2*)(wr + 4));
        ulonglong2 w3 = __ldg((const ulonglong2*)(wr + 6));
        u64t wv[8] = { w0.x, w0.y, w1.x, w1.y, w2.x, w2.y, w3.x, w3.y };
        #pragma unroll
        for (int mp = 0; mp < 4; mp++)
            #pragma unroll
            for (int j = 0; j < 8; j++) acc[mp][j] = fma2(ap[mp], wv[j], acc[mp][j]);
    }

    #pragma unroll
    for (int mp = 0; mp < 4; mp++){
        #pragma unroll
        for (int j = 0; j < 8; j++){
            float lo, hi; upk2(acc[mp][j], lo, hi);
            u64t t = pk2(fast_tanh(lo), fast_tanh(hi));
            *(u64t*)(Hout + (n0 + j)*ASTRIDE + m0 + 2*mp) = t;
        }
    }
}

// ============================================================
// Stage 1: blocks [0,1152) MLP; blocks [1152,1408) build AcatT (dup pairs).
// ============================================================
__global__ __launch_bounds__(128, 3)
void stage1(const float* __restrict__ nodes,
            const float* __restrict__ W1, const float* __restrict__ b1,
            const float* __restrict__ b2, const float* __restrict__ b3,
            const float* __restrict__ W4, const float* __restrict__ b4,
            const float* __restrict__ BDD,
            const float* __restrict__ Ixx, const float* __restrict__ Iyy,
            const float* __restrict__ wq,  const float* __restrict__ Base){
    extern __shared__ float sm[];
    const int tid = threadIdx.x;

    if (blockIdx.x >= MLP_BLOCKS){
        // ---------- build AcatT branch ----------
        const int s = blockIdx.x - MLP_BLOCKS;
        float* WB  = sm;
        float* sI0 = WB  + Q_*R_;
        float* sI1 = sI0 + Q_*NN_;

        for (int i = tid; i < Q_*R_; i += 128){
            int q = i / R_, r = i - q*R_;
            WB[i] = wq[q] * Base[q*R_ + r];
        }
        for (int i = tid; i < Q_*NN_; i += 128){
            sI0[i] = Ixx[s*Q_*NN_ + i];
            sI1[i] = Iyy[s*Q_*NN_ + i];
        }
        __syncthreads();

        for (int idx = tid; idx < R_*K2_; idx += 128){
            int r = idx / K2_, n = idx - r*K2_;
            const float* I = (n < NN_) ? sI0 : sI1;
            int nn = (n < NN_) ? n : (n - NN_);
            float acc = 0.f;
            #pragma unroll
            for (int q = 0; q < Q_; q++) acc += WB[q*R_ + r] * I[q*NN_ + nn];
            g_AcatT[n*SR_ + s*R_ + r] = pk2(acc, acc);
        }
        return;
    }

    // ---------- MLP branch ----------
    float* Ha = sm;                       // [128][ASTRIDE]
    float* Hb = sm + H_*ASTRIDE;
    __shared__ float xs[PPB][2];

    const int p0 = blockIdx.x * PPB;
    ((float*)xs)[tid] = nodes[p0*2 + tid];
    __syncthreads();

    for (int idx = tid; idx < H_*PPB; idx += 128){
        int j = idx >> 6, p = idx & 63;
        float pre = xs[p][0]*__ldg(&W1[j]) + xs[p][1]*__ldg(&W1[H_ + j]) + __ldg(&b1[j]);
        Ha[j*ASTRIDE + p] = fast_tanh(pre);
    }
    __syncthreads();

    gemm_layer64(Ha, Hb, g_Wdup,         b2);  __syncthreads();
    gemm_layer64(Hb, Ha, g_Wdup + H_*H_, b3);  __syncthreads();

    if (tid < PPB){
        float acc = 0.f;
        #pragma unroll 8
        for (int k = 0; k < H_; k++) acc += Ha[k*ASTRIDE + tid] * __ldg(&W4[k]);
        float ev = acc + __ldg(&b4[0]);
        int p = p0 + tid;
        int e = p / NN_, n = p - e*NN_;
        float c00 = __ldg(&BDD[e*4 + 0]), c01 = __ldg(&BDD[e*4 + 1]);
        float c10 = __ldg(&BDD[e*4 + 2]), c11 = __ldg(&BDD[e*4 + 3]);
        g_evcat[e*K2_ + n]       = (c00 + c10) * ev;
        g_evcat[e*K2_ + NN_ + n] = (c01 + c11) * ev;
    }
}

// ============================================================
// Stage 2: 64m x 128n tiles, 128 threads, m-packed 8m x 8n/thread.
// u = -J*(evcat @ Acat^T); fused loss; last-block final reduce.
// ============================================================
__global__ __launch_bounds__(128, 2)
void gemm_loss(const float* __restrict__ J, const float* __restrict__ F,
               float* __restrict__ out){
    extern __shared__ float sm[];
    float* As  = sm;                              // [72][ASTRIDE] floats, m fastest
    u64t*  Bsd = (u64t*)(sm + K2_*ASTRIDE);       // [72][BDSTRIDE] dup pairs, n fastest
    const int tid = threadIdx.x;
    const int m0g = blockIdx.y * 64, n0g = blockIdx.x * 128;

    for (int idx = tid; idx < 64*K2_; idx += 128){
        int m = idx / K2_, k = idx - m*K2_;
        As[k*ASTRIDE + m] = g_evcat[(m0g + m)*K2_ + k];
    }
    for (int idx = tid; idx < K2_*64; idx += 128){
        int k = idx / 64, n2 = (idx - k*64) * 2;
        ulonglong2 v = *(const ulonglong2*)(g_AcatT + k*SR_ + n0g + n2);
        *(ulonglong2*)(Bsd + k*BDSTRIDE + n2) = v;
    }
    __syncthreads();

    const int tx = tid & 15, ty = tid >> 4;   // n0 = tx*8, m0 = ty*8
    const int m0 = ty * 8, n0 = tx * 8;

    u64t acc[4][8];
    #pragma unroll
    for (int mp = 0; mp < 4; mp++)
        #pragma unroll
        for (int j = 0; j < 8; j++) acc[mp][j] = 0ULL;

    #pragma unroll 2
    for (int k = 0; k < K2_; k++){
        F4U a0, a1;
        a0.f = *(const float4*)(As + k*ASTRIDE + m0);
        a1.f = *(const float4*)(As + k*ASTRIDE + m0 + 4);
        u64t ap[4] = { a0.u[0], a0.u[1], a1.u[0], a1.u[1] };
        const u64t* br = Bsd + k*BDSTRIDE + n0;
        ulonglong2 b0 = *(const ulonglong2*)(br);
        ulonglong2 b1 = *(const ulonglong2*)(br + 2);
        ulonglong2 b2 = *(const ulonglong2*)(br + 4);
        ulonglong2 b3 = *(const ulonglong2*)(br + 6);
        u64t bv[8] = { b0.x, b0.y, b1.x, b1.y, b2.x, b2.y, b3.x, b3.y };
        #pragma unroll
        for (int mp = 0; mp < 4; mp++)
            #pragma unroll
            for (int j = 0; j < 8; j++) acc[mp][j] = fma2(ap[mp], bv[j], acc[mp][j]);
    }

    // fused epilogue: rows (e0,e1) per m-pair; res = -J*dot - F; sum res^2
    float lsum = 0.f;
    #pragma unroll
    for (int mp = 0; mp < 4; mp++){
        int e0 = m0g + m0 + 2*mp, e1 = e0 + 1;
        const float* F0 = F + e0*SR_ + n0g + n0;
        const float* F1 = F + e1*SR_ + n0g + n0;
        float4 f00 = __ldg((const float4*)(F0));
        float4 f01 = __ldg((const float4*)(F0 + 4));
        float4 f10 = __ldg((const float4*)(F1));
        float4 f11 = __ldg((const float4*)(F1 + 4));
        float fv0[8] = { f00.x,f00.y,f00.z,f00.w, f01.x,f01.y,f01.z,f01.w };
        float fv1[8] = { f10.x,f10.y,f10.z,f10.w, f11.x,f11.y,f11.z,f11.w };
        #pragma unroll
        for (int j = 0; j < 8; j++){
            float lo, hi; upk2(acc[mp][j], lo, hi);
            int n = n0g + n0 + j;
            int sidx = n / R_;
            float j0 = __ldg(&J[e0*S_ + sidx]);
            float j1 = __ldg(&J[e1*S_ + sidx]);
            float r0 = -j0*lo - fv0[j];
            float r1 = -j1*hi - fv1[j];
            lsum += r0*r0 + r1*r1;
        }
    }

    __shared__ float red[128];
    red[tid] = lsum; __syncthreads();
    #pragma unroll
    for (int s = 64; s > 0; s >>= 1){
        if (tid < s) red[tid] += red[tid + s];
        __syncthreads();
    }

    __shared__ unsigned s_last;
    if (tid == 0){
        g_partial[blockIdx.y * GX + blockIdx.x] = red[0];
        __threadfence();
        unsigned t = atomicAdd(&g_count, 1u);
        s_last = (t == NPART - 1u) ? 1u : 0u;
    }
    __syncthreads();

    if (s_last){
        __shared__ double dred[128];
        double s = 0.0;
        for (int i = tid; i < NPART; i += 128) s += (double)g_partial[i];
        dred[tid] = s; __syncthreads();
        #pragma unroll
        for (int k = 64; k > 0; k >>= 1){
            if (tid < k) dred[tid] += dred[tid + k];
            __syncthreads();
        }
        if (tid == 0){
            out[0] = (float)(dred[0] / (double)R_);
            g_count = 0;
        }
    }
}

// ============================================================
extern "C" void kernel_launch(void* const* d_in, const int* in_sizes, int n_in,
                              void* d_out, int out_size){
    const float* nodes = (const float*)d_in[0];
    const float* W1    = (const float*)d_in[1];
    const float* b1    = (const float*)d_in[2];
    const float* W2    = (const float*)d_in[3];
    const float* b2    = (const float*)d_in[4];
    const float* W3    = (const float*)d_in[5];
    const float* b3    = (const float*)d_in[6];
    const float* W4    = (const float*)d_in[7];
    const float* b4    = (const float*)d_in[8];
    const float* Ixx   = (const float*)d_in[9];
    const float* Iyy   = (const float*)d_in[10];
    const float* BDD   = (const float*)d_in[11];
    const float* wq    = (const float*)d_in[12];
    const float* Base  = (const float*)d_in[13];
    const float* J     = (const float*)d_in[14];
    const float* F     = (const float*)d_in[15];

    const int s1_smem   = 2 * H_ * ASTRIDE * 4;                      // 69632 B
    const int gemm_smem = K2_*ASTRIDE*4 + K2_*BDSTRIDE*8;            // 19584 + 74880 = 94464 B
    cudaFuncSetAttribute(stage1,    cudaFuncAttributeMaxDynamicSharedMemorySize, s1_smem);
    cudaFuncSetAttribute(gemm_loss, cudaFuncAttributeMaxDynamicSharedMemorySize, gemm_smem);

    dup_w<<<2*H_*H_/256, 256>>>(W2, W3);
    stage1<<<STAGE1_BLOCKS, 128, s1_smem>>>(nodes, W1, b1, b2, b3, W4, b4,
                                            BDD, Ixx, Iyy, wq, Base);
    gemm_loss<<<dim3(GX, GY), 128, gemm_smem>>>(J, F, (float*)d_out);
}